// round 2
// baseline (speedup 1.0000x reference)
#include <cuda_runtime.h>
#include <cuda_bf16.h>
#include <math.h>

// ---------------- problem constants ----------------
#define BATCH 4
#define NQ 4096
#define NL 1024
#define DV 512
#define DC 128
#define DI 512
#define DF 2048
#define NH 8
#define HD 64

// ---------------- device scratch ----------------
__device__ float g_sLv[BATCH * NL * DV];        //  8 MB
__device__ float g_sLc[BATCH * NL * DC];        //  2 MB
__device__ float g_vk [BATCH * NL * (2 * DI)];  // 16 MB  (v_v | k_v)
__device__ float g_kc [BATCH * NL * DI];        //  8 MB
__device__ float g_qv [BATCH * NQ * DI];        // 32 MB
__device__ float g_qc [BATCH * NQ * DI];        // 32 MB
__device__ float g_att[BATCH * NQ * DI];        // 32 MB
__device__ float g_y  [BATCH * NQ * DV];        // 32 MB
__device__ float g_h1 [BATCH * NQ * DF];        // 128 MB
__device__ float g_h2 [BATCH * NQ * DF];        // 128 MB

// ---------------- helpers ----------------
__device__ __forceinline__ float gelu_f(float x) {
    // jax.nn.gelu default (approximate=True, tanh form)
    float x3 = x * x * x;
    return 0.5f * x * (1.0f + tanhf(0.7978845608028654f * (x + 0.044715f * x3)));
}

// ---------------- LayerNorm (out-of-place ok, in-place ok) ----------------
__global__ void layernorm_kernel(const float* __restrict__ x,
                                 const float* __restrict__ g,
                                 const float* __restrict__ b,
                                 float* __restrict__ y,
                                 int D, float eps) {
    int row = blockIdx.x;
    const float* xr = x + (size_t)row * D;
    float s = 0.f, ss = 0.f;
    for (int i = threadIdx.x; i < D; i += blockDim.x) {
        float v = xr[i];
        s += v; ss += v * v;
    }
    __shared__ float rs[32], rss[32];
    #pragma unroll
    for (int off = 16; off; off >>= 1) {
        s  += __shfl_xor_sync(0xffffffffu, s,  off);
        ss += __shfl_xor_sync(0xffffffffu, ss, off);
    }
    int w = threadIdx.x >> 5, l = threadIdx.x & 31;
    if (l == 0) { rs[w] = s; rss[w] = ss; }
    __syncthreads();
    int nw = blockDim.x >> 5;
    if (threadIdx.x < 32) {
        s  = (l < nw) ? rs[l]  : 0.f;
        ss = (l < nw) ? rss[l] : 0.f;
        #pragma unroll
        for (int off = 16; off; off >>= 1) {
            s  += __shfl_xor_sync(0xffffffffu, s,  off);
            ss += __shfl_xor_sync(0xffffffffu, ss, off);
        }
        if (l == 0) { rs[0] = s; rss[0] = ss; }
    }
    __syncthreads();
    float mean = rs[0] / (float)D;
    float var  = rss[0] / (float)D - mean * mean;
    float inv  = rsqrtf(var + eps);
    float* yr = y + (size_t)row * D;
    for (int i = threadIdx.x; i < D; i += blockDim.x)
        yr[i] = (xr[i] - mean) * inv * g[i] + b[i];
}

// ---------------- RMSNorm in-place ----------------
__global__ void rmsnorm_kernel(float* __restrict__ x,
                               const float* __restrict__ g,
                               int D, float eps) {
    int row = blockIdx.x;
    float* xr = x + (size_t)row * D;
    float ss = 0.f;
    for (int i = threadIdx.x; i < D; i += blockDim.x) {
        float v = xr[i];
        ss += v * v;
    }
    __shared__ float rss[32];
    #pragma unroll
    for (int off = 16; off; off >>= 1)
        ss += __shfl_xor_sync(0xffffffffu, ss, off);
    int w = threadIdx.x >> 5, l = threadIdx.x & 31;
    if (l == 0) rss[w] = ss;
    __syncthreads();
    int nw = blockDim.x >> 5;
    if (threadIdx.x < 32) {
        ss = (l < nw) ? rss[l] : 0.f;
        #pragma unroll
        for (int off = 16; off; off >>= 1)
            ss += __shfl_xor_sync(0xffffffffu, ss, off);
        if (l == 0) rss[0] = ss;
    }
    __syncthreads();
    float inv = rsqrtf(rss[0] / (float)D + eps);
    for (int i = threadIdx.x; i < D; i += blockDim.x)
        xr[i] = xr[i] * inv * g[i];
}

// ---------------- generic tiled fp32 GEMM: C = A[M,K] @ W[K,N] + bias ----------------
// EPI: 0 = bias, 1 = bias + gelu
template <int EPI>
__global__ void gemm_kernel(const float* __restrict__ A,
                            const float* __restrict__ W,
                            const float* __restrict__ bias,
                            float* __restrict__ C,
                            int M, int K, int N) {
    __shared__ __align__(16) float As[16][68]; // [k][m] transposed
    __shared__ __align__(16) float Bs[16][68]; // [k][n]
    int tid = threadIdx.x;
    int tx = tid & 15, ty = tid >> 4;
    int bm = blockIdx.y * 64, bn = blockIdx.x * 64;
    float acc[4][4] = {};
    for (int k0 = 0; k0 < K; k0 += 16) {
        #pragma unroll
        for (int i = tid; i < 1024; i += 256) {
            int r = i >> 4, c = i & 15;
            As[c][r] = A[(size_t)(bm + r) * K + (k0 + c)];
        }
        #pragma unroll
        for (int i = tid; i < 1024; i += 256) {
            int r = i >> 6, c = i & 63;
            Bs[r][c] = W[(size_t)(k0 + r) * N + (bn + c)];
        }
        __syncthreads();
        #pragma unroll
        for (int kk = 0; kk < 16; kk++) {
            float4 a4 = *reinterpret_cast<const float4*>(&As[kk][ty * 4]);
            float4 b4 = *reinterpret_cast<const float4*>(&Bs[kk][tx * 4]);
            float a[4] = {a4.x, a4.y, a4.z, a4.w};
            float bb[4] = {b4.x, b4.y, b4.z, b4.w};
            #pragma unroll
            for (int i = 0; i < 4; i++)
                #pragma unroll
                for (int j = 0; j < 4; j++)
                    acc[i][j] += a[i] * bb[j];
        }
        __syncthreads();
    }
    #pragma unroll
    for (int i = 0; i < 4; i++) {
        int row = bm + ty * 4 + i;
        #pragma unroll
        for (int j = 0; j < 4; j++) {
            int col = bn + tx * 4 + j;
            float v = acc[i][j] + bias[col];
            if (EPI == 1) v = gelu_f(v);
            C[(size_t)row * N + col] = v;
        }
    }
}

// ---------------- fused dual-score flash attention ----------------
// score = q_c . k_c + lam * q_v . k_v == [q_c, lam*q_v] . [k_c, k_v]  (128-dim)
// grid: (NQ/64, H, B), 256 threads, online softmax, 64-wide kv tiles.
__global__ void attn_kernel(const float* __restrict__ qc,
                            const float* __restrict__ qv,
                            const float* __restrict__ kc,
                            const float* __restrict__ vkbuf, // [.,1024]: v_v | k_v
                            const float* __restrict__ lamp,
                            float* __restrict__ out) {
    int q0 = blockIdx.x * 64;
    int h  = blockIdx.y;
    int b  = blockIdx.z;
    extern __shared__ float smf[];
    float* Qs = smf;             // [64][129]
    float* Ks = Qs + 64 * 129;   // [64][129]
    float* Vs = Ks + 64 * 129;   // [64][65]
    float* Ps = Vs + 64 * 65;    // [64][65]

    int tid = threadIdx.x;
    int tx = tid & 15, ty = tid >> 4;
    float lam = lamp[0];

    for (int i = tid; i < 64 * 64; i += 256) {
        int r = i >> 6, d = i & 63;
        size_t base = ((size_t)(b * NQ + q0 + r)) * DI + h * HD + d;
        Qs[r * 129 + d]      = qc[base];
        Qs[r * 129 + 64 + d] = lam * qv[base];
    }

    float m_i[4], l_i[4], o[4][4];
    #pragma unroll
    for (int i = 0; i < 4; i++) {
        m_i[i] = -1e30f; l_i[i] = 0.f;
        #pragma unroll
        for (int j = 0; j < 4; j++) o[i][j] = 0.f;
    }

    for (int m0 = 0; m0 < NL; m0 += 64) {
        __syncthreads(); // protect Ks/Vs from prev PV; first iter: orders Q writes too
        for (int i = tid; i < 64 * 64; i += 256) {
            int r = i >> 6, d = i & 63;
            size_t kb = (size_t)(b * NL + m0 + r);
            Ks[r * 129 + d]      = kc[kb * DI + h * HD + d];
            Ks[r * 129 + 64 + d] = vkbuf[kb * (2 * DI) + DI + h * HD + d]; // k_v
            Vs[r * 65 + d]       = vkbuf[kb * (2 * DI) + h * HD + d];      // v_v
        }
        __syncthreads();

        float s[4][4];
        #pragma unroll
        for (int i = 0; i < 4; i++)
            #pragma unroll
            for (int j = 0; j < 4; j++) s[i][j] = 0.f;

        for (int kk = 0; kk < 128; kk++) {
            float a[4], bb[4];
            #pragma unroll
            for (int i = 0; i < 4; i++) a[i] = Qs[(ty * 4 + i) * 129 + kk];
            #pragma unroll
            for (int j = 0; j < 4; j++) bb[j] = Ks[(tx * 4 + j) * 129 + kk];
            #pragma unroll
            for (int i = 0; i < 4; i++)
                #pragma unroll
                for (int j = 0; j < 4; j++) s[i][j] += a[i] * bb[j];
        }

        // online softmax update (rows owned by 16 lanes of a half-warp)
        #pragma unroll
        for (int i = 0; i < 4; i++) {
            float mx = -1e30f;
            #pragma unroll
            for (int j = 0; j < 4; j++) {
                s[i][j] *= 0.125f; // 1/sqrt(64)
                mx = fmaxf(mx, s[i][j]);
            }
            #pragma unroll
            for (int off = 8; off; off >>= 1)
                mx = fmaxf(mx, __shfl_xor_sync(0xffffffffu, mx, off, 16));
            float mn = fmaxf(m_i[i], mx);
            float corr = __expf(m_i[i] - mn);
            float rsum = 0.f;
            #pragma unroll
            for (int j = 0; j < 4; j++) {
                float p = __expf(s[i][j] - mn);
                s[i][j] = p; rsum += p;
            }
            #pragma unroll
            for (int off = 8; off; off >>= 1)
                rsum += __shfl_xor_sync(0xffffffffu, rsum, off, 16);
            l_i[i] = l_i[i] * corr + rsum;
            m_i[i] = mn;
            #pragma unroll
            for (int j = 0; j < 4; j++) {
                o[i][j] *= corr;
                Ps[(ty * 4 + i) * 65 + tx * 4 + j] = s[i][j];
            }
        }
        __syncthreads();

        // O += P @ V
        for (int c = 0; c < 64; c++) {
            float a[4], bb[4];
            #pragma unroll
            for (int i = 0; i < 4; i++) a[i] = Ps[(ty * 4 + i) * 65 + c];
            #pragma unroll
            for (int j = 0; j < 4; j++) bb[j] = Vs[c * 65 + tx * 4 + j];
            #pragma unroll
            for (int i = 0; i < 4; i++)
                #pragma unroll
                for (int j = 0; j < 4; j++) o[i][j] += a[i] * bb[j];
        }
    }

    #pragma unroll
    for (int i = 0; i < 4; i++) {
        float invl = 1.f / l_i[i];
        int row = b * NQ + q0 + ty * 4 + i;
        #pragma unroll
        for (int j = 0; j < 4; j++)
            out[(size_t)row * DI + h * HD + tx * 4 + j] = o[i][j] * invl;
    }
}

// ---------------- host launcher ----------------
extern "C" void kernel_launch(void* const* d_in, const int* in_sizes, int n_in,
                              void* d_out, int out_size) {
    const float* coords = (const float*)d_in[0];
    const float* values = (const float*)d_in[1];
    const float* Lv     = (const float*)d_in[2];
    const float* Lc     = (const float*)d_in[3];
    const float* lam    = (const float*)d_in[4];
    const float* lvn_g  = (const float*)d_in[5];
    const float* lvn_b  = (const float*)d_in[6];
    const float* lcn_g  = (const float*)d_in[7];
    const float* lcn_b  = (const float*)d_in[8];
    const float* ck_w   = (const float*)d_in[9];
    const float* ck_b   = (const float*)d_in[10];
    const float* ck_g   = (const float*)d_in[11];
    const float* cq_w   = (const float*)d_in[12];
    const float* cq_b   = (const float*)d_in[13];
    const float* cq_g   = (const float*)d_in[14];
    const float* vq_w   = (const float*)d_in[15];
    const float* vq_b   = (const float*)d_in[16];
    const float* vq_g   = (const float*)d_in[17];
    const float* vk_w   = (const float*)d_in[18];
    const float* vk_b   = (const float*)d_in[19];
    const float* op_w   = (const float*)d_in[20];
    const float* op_b   = (const float*)d_in[21];
    const float* oln_g  = (const float*)d_in[22];
    const float* oln_b  = (const float*)d_in[23];
    const float* m1_w   = (const float*)d_in[24];
    const float* m1_b   = (const float*)d_in[25];
    const float* m2_w   = (const float*)d_in[26];
    const float* m2_b   = (const float*)d_in[27];
    const float* m3_w   = (const float*)d_in[28];
    const float* m3_b   = (const float*)d_in[29];
    float* out = (float*)d_out;

    float *sLv, *sLc, *vkb, *kcb, *qvb, *qcb, *attb, *yb, *h1, *h2;
    cudaGetSymbolAddress((void**)&sLv,  g_sLv);
    cudaGetSymbolAddress((void**)&sLc,  g_sLc);
    cudaGetSymbolAddress((void**)&vkb,  g_vk);
    cudaGetSymbolAddress((void**)&kcb,  g_kc);
    cudaGetSymbolAddress((void**)&qvb,  g_qv);
    cudaGetSymbolAddress((void**)&qcb,  g_qc);
    cudaGetSymbolAddress((void**)&attb, g_att);
    cudaGetSymbolAddress((void**)&yb,   g_y);
    cudaGetSymbolAddress((void**)&h1,   g_h1);
    cudaGetSymbolAddress((void**)&h2,   g_h2);

    const int BNL = BATCH * NL;   // 4096
    const int BNQ = BATCH * NQ;   // 16384

    // latent layernorms
    layernorm_kernel<<<BNL, 256>>>(Lv, lvn_g, lvn_b, sLv, DV, 1e-5f);
    layernorm_kernel<<<BNL, 128>>>(Lc, lcn_g, lcn_b, sLc, DC, 1e-5f);

    // projections
    gemm_kernel<0><<<dim3((2 * DI) / 64, BNL / 64), 256>>>(sLv, vk_w, vk_b, vkb, BNL, DV, 2 * DI);
    gemm_kernel<0><<<dim3(DI / 64, BNL / 64), 256>>>(sLc, ck_w, ck_b, kcb, BNL, DC, DI);
    rmsnorm_kernel<<<BNL, 256>>>(kcb, ck_g, DI, 1e-6f);
    gemm_kernel<0><<<dim3(DI / 64, BNQ / 64), 256>>>(values, vq_w, vq_b, qvb, BNQ, DV, DI);
    rmsnorm_kernel<<<BNQ, 256>>>(qvb, vq_g, DI, 1e-6f);
    gemm_kernel<0><<<dim3(DI / 64, BNQ / 64), 256>>>(coords, cq_w, cq_b, qcb, BNQ, DC, DI);
    rmsnorm_kernel<<<BNQ, 256>>>(qcb, cq_g, DI, 1e-6f);

    // dual-score flash attention
    size_t ash = (size_t)(64 * 129 * 2 + 64 * 65 * 2) * sizeof(float); // 99328 B
    cudaFuncSetAttribute(attn_kernel, cudaFuncAttributeMaxDynamicSharedMemorySize, (int)ash);
    attn_kernel<<<dim3(NQ / 64, NH, BATCH), 256, ash>>>(qcb, qvb, kcb, vkb, lam, attb);

    // output projection + LN + MLP
    gemm_kernel<0><<<dim3(DV / 64, BNQ / 64), 256>>>(attb, op_w, op_b, yb, BNQ, DI, DV);
    layernorm_kernel<<<BNQ, 256>>>(yb, oln_g, oln_b, yb, DV, 1e-5f);
    gemm_kernel<1><<<dim3(DF / 64, BNQ / 64), 256>>>(yb, m1_w, m1_b, h1, BNQ, DV, DF);
    gemm_kernel<1><<<dim3(DF / 64, BNQ / 64), 256>>>(h1, m2_w, m2_b, h2, BNQ, DF, DF);
    gemm_kernel<0><<<dim3(DV / 64, BNQ / 64), 256>>>(h2, m3_w, m3_b, out, BNQ, DF, DV);
}

// round 3
// speedup vs baseline: 5.1825x; 5.1825x over previous
#include <cuda_runtime.h>
#include <math.h>

#define BATCH 4
#define NQ 4096
#define NL 1024
#define DV 512
#define DC 128
#define DI 512
#define DF 2048
#define NH 8
#define HD 64

// ---------------- device scratch ----------------
__device__ float g_sLv[BATCH * NL * DV];
__device__ float g_sLc[BATCH * NL * DC];
__device__ float g_vk [BATCH * NL * (2 * DI)];
__device__ float g_kc [BATCH * NL * DI];
__device__ float g_qv [BATCH * NQ * DI];
__device__ float g_qc [BATCH * NQ * DI];
__device__ float g_att[BATCH * NQ * DI];
__device__ float g_y  [BATCH * NQ * DV];
__device__ float g_h1 [BATCH * NQ * DF];
__device__ float g_h2 [BATCH * NQ * DF];
__device__ float g_kt [BATCH * NH * 128 * NL];
__device__ float g_rv [BATCH * NQ * DV];
__device__ float g_rc [BATCH * NQ * DC];
__device__ float g_wr [7471104];

#define OFF_CKW 0
#define OFF_CQW 65536
#define OFF_VQW 131072
#define OFF_VKW 393216
#define OFF_OPW 917504
#define OFF_M1W 1179648
#define OFF_M2W 2228224
#define OFF_M3W 6422528

__device__ __forceinline__ float gelu_f(float x) {
    float x3 = x * x * x;
    return 0.5f * x * (1.0f + tanhf(0.7978845608028654f * (x + 0.044715f * x3)));
}
__device__ __forceinline__ unsigned f2tf(float x) {
    unsigned u; asm("cvt.rna.tf32.f32 %0, %1;" : "=r"(u) : "f"(x)); return u;
}
__device__ __forceinline__ float tfbits(float x) { return __uint_as_float(f2tf(x)); }

__device__ __forceinline__ void mma_tf32(float* c, const unsigned* a, unsigned b0, unsigned b1) {
    asm volatile(
        "mma.sync.aligned.m16n8k8.row.col.f32.tf32.tf32.f32 "
        "{%0,%1,%2,%3},{%4,%5,%6,%7},{%8,%9},{%0,%1,%2,%3};"
        : "+f"(c[0]), "+f"(c[1]), "+f"(c[2]), "+f"(c[3])
        : "r"(a[0]), "r"(a[1]), "r"(a[2]), "r"(a[3]), "r"(b0), "r"(b1));
}
__device__ __forceinline__ void ldsm4(unsigned* r, unsigned addr) {
    asm volatile("ldmatrix.sync.aligned.m8n8.x4.shared.b16 {%0,%1,%2,%3}, [%4];"
        : "=r"(r[0]), "=r"(r[1]), "=r"(r[2]), "=r"(r[3]) : "r"(addr));
}
__device__ __forceinline__ void cpa16(unsigned dst, const void* src) {
    asm volatile("cp.async.cg.shared.global [%0], [%1], 16;" :: "r"(dst), "l"(src));
}
__device__ __forceinline__ void cpa_commit() { asm volatile("cp.async.commit_group;"); }
__device__ __forceinline__ unsigned sh_addr(const void* p) {
    return (unsigned)__cvta_generic_to_shared(p);
}

// ---------------- tf32 rounding copy ----------------
__global__ void round_copy(const float* __restrict__ x, float* __restrict__ y, int n4) {
    int i = blockIdx.x * blockDim.x + threadIdx.x;
    if (i < n4) {
        float4 v = ((const float4*)x)[i];
        v.x = tfbits(v.x); v.y = tfbits(v.y); v.z = tfbits(v.z); v.w = tfbits(v.w);
        ((float4*)y)[i] = v;
    }
}

// ---------------- LayerNorm (tf32-rounded output) ----------------
__global__ void layernorm_kernel(const float* __restrict__ x, const float* __restrict__ g,
                                 const float* __restrict__ b, float* __restrict__ y,
                                 int D, float eps) {
    int row = blockIdx.x;
    const float* xr = x + (size_t)row * D;
    float s = 0.f, ss = 0.f;
    for (int i = threadIdx.x; i < D; i += blockDim.x) { float v = xr[i]; s += v; ss += v * v; }
    __shared__ float rs[32], rss[32];
    #pragma unroll
    for (int off = 16; off; off >>= 1) {
        s  += __shfl_xor_sync(0xffffffffu, s,  off);
        ss += __shfl_xor_sync(0xffffffffu, ss, off);
    }
    int w = threadIdx.x >> 5, l = threadIdx.x & 31;
    if (l == 0) { rs[w] = s; rss[w] = ss; }
    __syncthreads();
    int nw = blockDim.x >> 5;
    if (threadIdx.x < 32) {
        s  = (l < nw) ? rs[l]  : 0.f;
        ss = (l < nw) ? rss[l] : 0.f;
        #pragma unroll
        for (int off = 16; off; off >>= 1) {
            s  += __shfl_xor_sync(0xffffffffu, s,  off);
            ss += __shfl_xor_sync(0xffffffffu, ss, off);
        }
        if (l == 0) { rs[0] = s; rss[0] = ss; }
    }
    __syncthreads();
    float mean = rs[0] / (float)D;
    float inv  = rsqrtf(rss[0] / (float)D - mean * mean + eps);
    float* yr = y + (size_t)row * D;
    for (int i = threadIdx.x; i < D; i += blockDim.x)
        yr[i] = tfbits((xr[i] - mean) * inv * g[i] + b[i]);
}

// ---------------- RMSNorm in-place (rounded, extra scale) ----------------
__global__ void rmsnorm_kernel(float* __restrict__ x, const float* __restrict__ g,
                               int D, float eps, float scale) {
    int row = blockIdx.x;
    float* xr = x + (size_t)row * D;
    float ss = 0.f;
    for (int i = threadIdx.x; i < D; i += blockDim.x) { float v = xr[i]; ss += v * v; }
    __shared__ float rss[32];
    #pragma unroll
    for (int off = 16; off; off >>= 1) ss += __shfl_xor_sync(0xffffffffu, ss, off);
    int w = threadIdx.x >> 5, l = threadIdx.x & 31;
    if (l == 0) rss[w] = ss;
    __syncthreads();
    int nw = blockDim.x >> 5;
    if (threadIdx.x < 32) {
        ss = (l < nw) ? rss[l] : 0.f;
        #pragma unroll
        for (int off = 16; off; off >>= 1) ss += __shfl_xor_sync(0xffffffffu, ss, off);
        if (l == 0) rss[0] = ss;
    }
    __syncthreads();
    float inv = rsqrtf(rss[0] / (float)D + eps) * scale;
    for (int i = threadIdx.x; i < D; i += blockDim.x)
        xr[i] = tfbits(xr[i] * inv * g[i]);
}

// ---------------- K transpose into g_kt[(b,h)][dBase+d][j] ----------------
__global__ void ktrans_kernel(const float* __restrict__ src, float* __restrict__ dst,
                              int srcStride, int colBase, int dBase,
                              const float* __restrict__ lamp, int useLam) {
    __shared__ float t[32][33];
    int bh = blockIdx.z; int b = bh >> 3; int h = bh & 7;
    int j0 = blockIdx.x * 32, d0 = blockIdx.y * 32;
    int tx = threadIdx.x, ty = threadIdx.y;
    float lam = useLam ? lamp[0] : 1.f;
    const float* s = src + ((size_t)(b * NL + j0)) * srcStride + colBase + h * HD + d0;
    for (int dy = ty; dy < 32; dy += 8)
        t[dy][tx] = s[(size_t)dy * srcStride + tx];
    __syncthreads();
    for (int dy = ty; dy < 32; dy += 8)
        dst[((size_t)(bh * 128 + dBase + d0 + dy)) * NL + j0 + tx] = tfbits(lam * t[tx][dy]);
}

// ---------------- tf32 tensor-core GEMM 128x128x32, 3-stage ----------------
#define GSTAGES 3
#define ASTR 36
#define BSTR 136
template <int EPI>  // 0=bias, 1=bias+gelu+round, 2=bias+round
__global__ void __launch_bounds__(256) gemm_tc(const float* __restrict__ A,
                                               const float* __restrict__ W,
                                               const float* __restrict__ bias,
                                               float* __restrict__ C,
                                               int M, int K, int N) {
    extern __shared__ float sm[];
    float* As = sm;
    float* Bs = sm + GSTAGES * 128 * ASTR;
    const int tid = threadIdx.x;
    const int bm = blockIdx.y * 128, bn = blockIdx.x * 128;
    const int warp = tid >> 5, lane = tid & 31;
    const int wm = (warp & 3) * 32, wn = (warp >> 2) * 64;
    const int g = lane >> 2, tg = lane & 3;
    const int KT = K >> 5;
    const unsigned asb = sh_addr(As), bsb = sh_addr(Bs);

    float acc[2][8][4];
    #pragma unroll
    for (int i = 0; i < 2; i++)
        #pragma unroll
        for (int j = 0; j < 8; j++)
            #pragma unroll
            for (int k = 0; k < 4; k++) acc[i][j][k] = 0.f;

    auto load_stage = [&](int s, int kt) {
        const float* Ag = A + (size_t)bm * K + kt * 32;
        const float* Wg = W + (size_t)(kt * 32) * N + bn;
        unsigned sa = asb + s * (128 * ASTR * 4);
        unsigned sb = bsb + s * (32 * BSTR * 4);
        #pragma unroll
        for (int i = 0; i < 4; i++) {
            int idx = tid + i * 256;
            int r = idx >> 3, q = idx & 7;
            cpa16(sa + (unsigned)(r * ASTR + q * 4) * 4, Ag + (size_t)r * K + q * 4);
        }
        #pragma unroll
        for (int i = 0; i < 4; i++) {
            int idx = tid + i * 256;
            int r = idx >> 5, q = idx & 31;
            cpa16(sb + (unsigned)(r * BSTR + q * 4) * 4, Wg + (size_t)r * N + q * 4);
        }
        cpa_commit();
    };

    load_stage(0, 0);
    if (KT > 1) load_stage(1, 1);

    const int lrow = (lane & 7) + ((lane >> 3) & 1) * 8;
    const int lcol = (lane >> 4) * 4;

    for (int kt = 0; kt < KT; kt++) {
        if (kt < KT - 1) asm volatile("cp.async.wait_group 1;");
        else             asm volatile("cp.async.wait_group 0;");
        __syncthreads();
        int s = kt % GSTAGES;
        if (kt + 2 < KT) load_stage((kt + 2) % GSTAGES, kt + 2);
        const float* bs_ = Bs + s * 32 * BSTR;
        unsigned abase = asb + s * (128 * ASTR * 4);
        #pragma unroll
        for (int ks = 0; ks < 4; ks++) {
            int k0 = ks * 8;
            unsigned a[2][4];
            #pragma unroll
            for (int mf = 0; mf < 2; mf++)
                ldsm4(a[mf], abase + (unsigned)((wm + mf * 16 + lrow) * ASTR + k0 + lcol) * 4);
            #pragma unroll
            for (int nf = 0; nf < 8; nf++) {
                unsigned b0 = __float_as_uint(bs_[(k0 + tg) * BSTR + wn + nf * 8 + g]);
                unsigned b1 = __float_as_uint(bs_[(k0 + tg + 4) * BSTR + wn + nf * 8 + g]);
                mma_tf32(acc[0][nf], a[0], b0, b1);
                mma_tf32(acc[1][nf], a[1], b0, b1);
            }
        }
        __syncthreads();
    }

    #pragma unroll
    for (int mf = 0; mf < 2; mf++) {
        int row = bm + wm + mf * 16 + g;
        #pragma unroll
        for (int nf = 0; nf < 8; nf++) {
            int col = bn + wn + nf * 8 + tg * 2;
            float b0v = bias[col], b1v = bias[col + 1];
            float v00 = acc[mf][nf][0] + b0v, v01 = acc[mf][nf][1] + b1v;
            float v10 = acc[mf][nf][2] + b0v, v11 = acc[mf][nf][3] + b1v;
            if (EPI == 1) { v00 = gelu_f(v00); v01 = gelu_f(v01); v10 = gelu_f(v10); v11 = gelu_f(v11); }
            if (EPI >= 1) { v00 = tfbits(v00); v01 = tfbits(v01); v10 = tfbits(v10); v11 = tfbits(v11); }
            *(float2*)&C[(size_t)row * N + col]       = make_float2(v00, v01);
            *(float2*)&C[(size_t)(row + 8) * N + col] = make_float2(v10, v11);
        }
    }
}

// ---------------- tensor-core dual-score flash attention ----------------
#define QSTR 132
#define KSTR 72
#define PSTR 68
__global__ void __launch_bounds__(256) attn_tc(const float* __restrict__ Qc,
                                               const float* __restrict__ Qv,
                                               const float* __restrict__ Kt,
                                               const float* __restrict__ Vsrc,
                                               float* __restrict__ out) {
    extern __shared__ float sm[];
    float* Qs = sm;                       // [128][QSTR]
    float* Ks = Qs + 128 * QSTR;          // [2][128][KSTR]  (d-major)
    float* Vs = Ks + 2 * 128 * KSTR;      // [2][64][KSTR]
    float* Ps = Vs + 2 * 64 * KSTR;       // [128][PSTR]
    const int tid = threadIdx.x, warp = tid >> 5, lane = tid & 31;
    const int g = lane >> 2, tg = lane & 3;
    const int q0 = blockIdx.x * 128, h = blockIdx.y, b = blockIdx.z;
    const int bh = b * NH + h;
    const unsigned qsb = sh_addr(Qs), ksb = sh_addr(Ks), vsb = sh_addr(Vs), psb = sh_addr(Ps);

    const float* qcb_ = Qc + ((size_t)(b * NQ + q0)) * DI + h * HD;
    const float* qvb_ = Qv + ((size_t)(b * NQ + q0)) * DI + h * HD;
    #pragma unroll
    for (int i = 0; i < 16; i++) {
        int idx = tid + i * 256;
        int r = idx >> 5, q = idx & 31;
        const float* src = (q < 16) ? (qcb_ + (size_t)r * DI + q * 4)
                                    : (qvb_ + (size_t)r * DI + (q - 16) * 4);
        cpa16(qsb + (unsigned)(r * QSTR + q * 4) * 4, src);
    }
    cpa_commit();

    const float* ktb = Kt + (size_t)bh * 128 * NL;
    const float* vvb = Vsrc + (size_t)b * NL * (2 * DI) + h * HD;
    auto load_kv = [&](int s, int m0) {
        unsigned ks_ = ksb + s * (128 * KSTR * 4);
        unsigned vs_ = vsb + s * (64 * KSTR * 4);
        #pragma unroll
        for (int i = 0; i < 8; i++) {
            int idx = tid + i * 256;
            int r = idx >> 4, q = idx & 15;
            cpa16(ks_ + (unsigned)(r * KSTR + q * 4) * 4, ktb + (size_t)r * NL + m0 + q * 4);
        }
        #pragma unroll
        for (int i = 0; i < 4; i++) {
            int idx = tid + i * 256;
            int r = idx >> 4, q = idx & 15;
            cpa16(vs_ + (unsigned)(r * KSTR + q * 4) * 4, vvb + (size_t)(m0 + r) * (2 * DI) + q * 4);
        }
        cpa_commit();
    };
    load_kv(0, 0);
    load_kv(1, 64);

    float m_[2] = {-1e30f, -1e30f}, l_[2] = {0.f, 0.f};
    float o[8][4];
    #pragma unroll
    for (int i = 0; i < 8; i++)
        #pragma unroll
        for (int j = 0; j < 4; j++) o[i][j] = 0.f;

    const int wrow = warp * 16;
    const int lrow = (lane & 7) + ((lane >> 3) & 1) * 8;
    const int lcol = (lane >> 4) * 4;
    const int NIT = NL / 64;

    for (int it = 0; it < NIT; it++) {
        if (it < NIT - 1) asm volatile("cp.async.wait_group 1;");
        else              asm volatile("cp.async.wait_group 0;");
        __syncthreads();
        int s = it & 1;
        const float* ksp = Ks + s * 128 * KSTR;
        const float* vsp = Vs + s * 64 * KSTR;

        float sacc[8][4];
        #pragma unroll
        for (int i = 0; i < 8; i++)
            #pragma unroll
            for (int j = 0; j < 4; j++) sacc[i][j] = 0.f;
        #pragma unroll
        for (int ks2 = 0; ks2 < 16; ks2++) {
            int k0 = ks2 * 8;
            unsigned a[4];
            ldsm4(a, qsb + (unsigned)((wrow + lrow) * QSTR + k0 + lcol) * 4);
            #pragma unroll
            for (int nf = 0; nf < 8; nf++) {
                unsigned b0 = __float_as_uint(ksp[(k0 + tg) * KSTR + nf * 8 + g]);
                unsigned b1 = __float_as_uint(ksp[(k0 + tg + 4) * KSTR + nf * 8 + g]);
                mma_tf32(sacc[nf], a, b0, b1);
            }
        }

        #pragma unroll
        for (int rw = 0; rw < 2; rw++) {
            float mx = -1e30f;
            #pragma unroll
            for (int nf = 0; nf < 8; nf++)
                mx = fmaxf(mx, fmaxf(sacc[nf][2 * rw], sacc[nf][2 * rw + 1]));
            mx = fmaxf(mx, __shfl_xor_sync(0xffffffffu, mx, 1));
            mx = fmaxf(mx, __shfl_xor_sync(0xffffffffu, mx, 2));
            float mn = fmaxf(m_[rw], mx);
            float corr = __expf(m_[rw] - mn);
            m_[rw] = mn;
            float sum = 0.f;
            int prow = wrow + rw * 8 + g;
            #pragma unroll
            for (int nf = 0; nf < 8; nf++) {
                float p0 = __expf(sacc[nf][2 * rw] - mn);
                float p1 = __expf(sacc[nf][2 * rw + 1] - mn);
                sum += p0 + p1;
                *(uint2*)(Ps + prow * PSTR + nf * 8 + tg * 2) = make_uint2(f2tf(p0), f2tf(p1));
            }
            sum += __shfl_xor_sync(0xffffffffu, sum, 1);
            sum += __shfl_xor_sync(0xffffffffu, sum, 2);
            l_[rw] = l_[rw] * corr + sum;
            #pragma unroll
            for (int nf = 0; nf < 8; nf++) {
                o[nf][2 * rw]     *= corr;
                o[nf][2 * rw + 1] *= corr;
            }
        }
        __syncwarp();

        #pragma unroll
        for (int ks2 = 0; ks2 < 8; ks2++) {
            int k0 = ks2 * 8;
            unsigned a[4];
            ldsm4(a, psb + (unsigned)((wrow + lrow) * PSTR + k0 + lcol) * 4);
            #pragma unroll
            for (int nf = 0; nf < 8; nf++) {
                unsigned b0 = __float_as_uint(vsp[(k0 + tg) * KSTR + nf * 8 + g]);
                unsigned b1 = __float_as_uint(vsp[(k0 + tg + 4) * KSTR + nf * 8 + g]);
                mma_tf32(o[nf], a, b0, b1);
            }
        }
        __syncthreads();
        if (it + 2 < NIT) load_kv(s, (it + 2) * 64);
    }

    #pragma unroll
    for (int rw = 0; rw < 2; rw++) {
        float inv = 1.f / l_[rw];
        int row = b * NQ + q0 + wrow + rw * 8 + g;
        #pragma unroll
        for (int nf = 0; nf < 8; nf++) {
            int col = h * HD + nf * 8 + tg * 2;
            *(float2*)&out[(size_t)row * DI + col] =
                make_float2(tfbits(o[nf][2 * rw] * inv), tfbits(o[nf][2 * rw + 1] * inv));
        }
    }
}

// ---------------- host launcher ----------------
extern "C" void kernel_launch(void* const* d_in, const int* in_sizes, int n_in,
                              void* d_out, int out_size) {
    const float* coords = (const float*)d_in[0];
    const float* values = (const float*)d_in[1];
    const float* Lv     = (const float*)d_in[2];
    const float* Lc     = (const float*)d_in[3];
    const float* lam    = (const float*)d_in[4];
    const float* lvn_g  = (const float*)d_in[5];
    const float* lvn_b  = (const float*)d_in[6];
    const float* lcn_g  = (const float*)d_in[7];
    const float* lcn_b  = (const float*)d_in[8];
    const float* ck_w   = (const float*)d_in[9];
    const float* ck_b   = (const float*)d_in[10];
    const float* ck_g   = (const float*)d_in[11];
    const float* cq_w   = (const float*)d_in[12];
    const float* cq_b   = (const float*)d_in[13];
    const float* cq_g   = (const float*)d_in[14];
    const float* vq_w   = (const float*)d_in[15];
    const float* vq_b   = (const float*)d_in[16];
    const float* vq_g   = (const float*)d_in[17];
    const float* vk_w   = (const float*)d_in[18];
    const float* vk_b   = (const float*)d_in[19];
    const float* op_w   = (const float*)d_in[20];
    const float* op_b   = (const float*)d_in[21];
    const float* oln_g  = (const float*)d_in[22];
    const float* oln_b  = (const float*)d_in[23];
    const float* m1_w   = (const float*)d_in[24];
    const float* m1_b   = (const float*)d_in[25];
    const float* m2_w   = (const float*)d_in[26];
    const float* m2_b   = (const float*)d_in[27];
    const float* m3_w   = (const float*)d_in[28];
    const float* m3_b   = (const float*)d_in[29];
    float* out = (float*)d_out;

    float *sLv, *sLc, *vkb, *kcb, *qvb, *qcb, *attb, *yb, *h1, *h2, *ktb, *rv, *rc, *wr;
    cudaGetSymbolAddress((void**)&sLv,  g_sLv);
    cudaGetSymbolAddress((void**)&sLc,  g_sLc);
    cudaGetSymbolAddress((void**)&vkb,  g_vk);
    cudaGetSymbolAddress((void**)&kcb,  g_kc);
    cudaGetSymbolAddress((void**)&qvb,  g_qv);
    cudaGetSymbolAddress((void**)&qcb,  g_qc);
    cudaGetSymbolAddress((void**)&attb, g_att);
    cudaGetSymbolAddress((void**)&yb,   g_y);
    cudaGetSymbolAddress((void**)&h1,   g_h1);
    cudaGetSymbolAddress((void**)&h2,   g_h2);
    cudaGetSymbolAddress((void**)&ktb,  g_kt);
    cudaGetSymbolAddress((void**)&rv,   g_rv);
    cudaGetSymbolAddress((void**)&rc,   g_rc);
    cudaGetSymbolAddress((void**)&wr,   g_wr);

    const int BNL = BATCH * NL;
    const int BNQ = BATCH * NQ;

    const int GEMM_SMEM = (GSTAGES * 128 * ASTR + GSTAGES * 32 * BSTR) * 4;
    const int ATTN_SMEM = (128 * QSTR + 2 * 128 * KSTR + 2 * 64 * KSTR + 128 * PSTR) * 4;
    cudaFuncSetAttribute(gemm_tc<0>, cudaFuncAttributeMaxDynamicSharedMemorySize, GEMM_SMEM);
    cudaFuncSetAttribute(gemm_tc<1>, cudaFuncAttributeMaxDynamicSharedMemorySize, GEMM_SMEM);
    cudaFuncSetAttribute(gemm_tc<2>, cudaFuncAttributeMaxDynamicSharedMemorySize, GEMM_SMEM);
    cudaFuncSetAttribute(attn_tc,    cudaFuncAttributeMaxDynamicSharedMemorySize, ATTN_SMEM);

    // one-time tf32 rounding of raw inputs & weights
    round_copy<<<BNQ * DV / 4 / 256, 256>>>(values, rv, BNQ * DV / 4);
    round_copy<<<BNQ * DC / 4 / 256, 256>>>(coords, rc, BNQ * DC / 4);
    round_copy<<<DC * DI / 4 / 256, 256>>>(ck_w, wr + OFF_CKW, DC * DI / 4);
    round_copy<<<DC * DI / 4 / 256, 256>>>(cq_w, wr + OFF_CQW, DC * DI / 4);
    round_copy<<<DV * DI / 4 / 256, 256>>>(vq_w, wr + OFF_VQW, DV * DI / 4);
    round_copy<<<DV * 2 * DI / 4 / 256, 256>>>(vk_w, wr + OFF_VKW, DV * 2 * DI / 4);
    round_copy<<<DI * DV / 4 / 256, 256>>>(op_w, wr + OFF_OPW, DI * DV / 4);
    round_copy<<<DV * DF / 4 / 256, 256>>>(m1_w, wr + OFF_M1W, DV * DF / 4);
    round_copy<<<DF * DF / 4 / 256, 256>>>(m2_w, wr + OFF_M2W, DF * DF / 4);
    round_copy<<<DF * DV / 4 / 256, 256>>>(m3_w, wr + OFF_M3W, DF * DV / 4);

    // latent layernorms (round outputs)
    layernorm_kernel<<<BNL, 256>>>(Lv, lvn_g, lvn_b, sLv, DV, 1e-5f);
    layernorm_kernel<<<BNL, 128>>>(Lc, lcn_g, lcn_b, sLc, DC, 1e-5f);

    // projections
    gemm_tc<2><<<dim3(8, 32), 256, GEMM_SMEM>>>(sLv, wr + OFF_VKW, vk_b, vkb, BNL, DV, 2 * DI);
    gemm_tc<0><<<dim3(4, 32), 256, GEMM_SMEM>>>(sLc, wr + OFF_CKW, ck_b, kcb, BNL, DC, DI);
    rmsnorm_kernel<<<BNL, 256>>>(kcb, ck_g, DI, 1e-6f, 1.0f);
    gemm_tc<0><<<dim3(4, 128), 256, GEMM_SMEM>>>(rv, wr + OFF_VQW, vq_b, qvb, BNQ, DV, DI);
    rmsnorm_kernel<<<BNQ, 256>>>(qvb, vq_g, DI, 1e-6f, 0.125f);
    gemm_tc<0><<<dim3(4, 128), 256, GEMM_SMEM>>>(rc, wr + OFF_CQW, cq_b, qcb, BNQ, DC, DI);
    rmsnorm_kernel<<<BNQ, 256>>>(qcb, cq_g, DI, 1e-6f, 0.125f);

    // K transposes (k_c plain, k_v scaled by lambda)
    dim3 tb(32, 8);
    ktrans_kernel<<<dim3(NL / 32, 2, BATCH * NH), tb>>>(kcb, ktb, DI, 0, 0, lam, 0);
    ktrans_kernel<<<dim3(NL / 32, 2, BATCH * NH), tb>>>(vkb, ktb, 2 * DI, DI, 64, lam, 1);

    // attention
    attn_tc<<<dim3(NQ / 128, NH, BATCH), 256, ATTN_SMEM>>>(qcb, qvb, ktb, vkb, attb);

    // output projection + LN + MLP
    gemm_tc<0><<<dim3(4, 128), 256, GEMM_SMEM>>>(attb, wr + OFF_OPW, op_b, yb, BNQ, DI, DV);
    layernorm_kernel<<<BNQ, 256>>>(yb, oln_g, oln_b, yb, DV, 1e-5f);
    gemm_tc<1><<<dim3(16, 128), 256, GEMM_SMEM>>>(yb, wr + OFF_M1W, m1_b, h1, BNQ, DV, DF);
    gemm_tc<1><<<dim3(16, 128), 256, GEMM_SMEM>>>(h1, wr + OFF_M2W, m2_b, h2, BNQ, DF, DF);
    gemm_tc<0><<<dim3(4, 128), 256, GEMM_SMEM>>>(h2, wr + OFF_M3W, m3_b, out, BNQ, DF, DV);
}

// round 5
// speedup vs baseline: 6.1138x; 1.1797x over previous
#include <cuda_runtime.h>
#include <cuda_fp16.h>
#include <math.h>
#include <cstdint>

#define BATCH 4
#define NQ 4096
#define NL 1024
#define DV 512
#define DC 128
#define DI 512
#define DF 2048
#define NH 8
#define HD 64

// ---------------- device scratch ----------------
__device__ float g_vk [BATCH * NL * (2 * DI)];
__device__ float g_kc [BATCH * NL * DI];
__device__ float g_qv [BATCH * NQ * DI];
__device__ float g_qc [BATCH * NQ * DI];
__device__ float g_y  [BATCH * NQ * DV];
__device__ float g_kt [BATCH * NH * 128 * NL];
__device__ __align__(16) __half g_sLv_h[BATCH * NL * DV], g_sLv_l[BATCH * NL * DV];
__device__ __align__(16) __half g_sLc_h[BATCH * NL * DC], g_sLc_l[BATCH * NL * DC];
__device__ __align__(16) __half g_val_h[BATCH * NQ * DV], g_val_l[BATCH * NQ * DV];
__device__ __align__(16) __half g_crd_h[BATCH * NQ * DC], g_crd_l[BATCH * NQ * DC];
__device__ __align__(16) __half g_att_h[BATCH * NQ * DI], g_att_l[BATCH * NQ * DI];
__device__ __align__(16) __half g_ybs_h[BATCH * NQ * DV], g_ybs_l[BATCH * NQ * DV];
__device__ __align__(16) __half g_h1_h[BATCH * NQ * DF];
__device__ __align__(16) __half g_h2_h[BATCH * NQ * DF];
__device__ __align__(16) __half g_wth[7471104], g_wtl[7471104];

#define OFF_CKW 0
#define OFF_CQW 65536
#define OFF_VQW 131072
#define OFF_VKW 393216
#define OFF_OPW 917504
#define OFF_M1W 1179648
#define OFF_M2W 2228224
#define OFF_M3W 6422528

// ---------------- helpers ----------------
__device__ __forceinline__ float gelu_f(float x) {
    float x3 = x * x * x;
    return 0.5f * x * (1.0f + tanhf(0.7978845608028654f * (x + 0.044715f * x3)));
}
__device__ __forceinline__ unsigned f2tf(float x) {
    unsigned u; asm("cvt.rna.tf32.f32 %0, %1;" : "=r"(u) : "f"(x)); return u;
}
__device__ __forceinline__ float tfbits(float x) { return __uint_as_float(f2tf(x)); }
__device__ __forceinline__ void split2h(float x, __half& h, __half& l) {
    h = __float2half_rn(x);
    l = __float2half_rn(x - __half2float(h));
}
__device__ __forceinline__ void mma_tf32(float* c, const unsigned* a, unsigned b0, unsigned b1) {
    asm volatile(
        "mma.sync.aligned.m16n8k8.row.col.f32.tf32.tf32.f32 "
        "{%0,%1,%2,%3},{%4,%5,%6,%7},{%8,%9},{%0,%1,%2,%3};"
        : "+f"(c[0]), "+f"(c[1]), "+f"(c[2]), "+f"(c[3])
        : "r"(a[0]), "r"(a[1]), "r"(a[2]), "r"(a[3]), "r"(b0), "r"(b1));
}
__device__ __forceinline__ void mma_f16(float* c, const unsigned* a, unsigned b0, unsigned b1) {
    asm volatile(
        "mma.sync.aligned.m16n8k16.row.col.f32.f16.f16.f32 "
        "{%0,%1,%2,%3},{%4,%5,%6,%7},{%8,%9},{%0,%1,%2,%3};"
        : "+f"(c[0]), "+f"(c[1]), "+f"(c[2]), "+f"(c[3])
        : "r"(a[0]), "r"(a[1]), "r"(a[2]), "r"(a[3]), "r"(b0), "r"(b1));
}
__device__ __forceinline__ void ldsm4(unsigned* r, unsigned addr) {
    asm volatile("ldmatrix.sync.aligned.m8n8.x4.shared.b16 {%0,%1,%2,%3}, [%4];"
        : "=r"(r[0]), "=r"(r[1]), "=r"(r[2]), "=r"(r[3]) : "r"(addr));
}
__device__ __forceinline__ void cpa16(unsigned dst, const void* src) {
    asm volatile("cp.async.cg.shared.global [%0], [%1], 16;" :: "r"(dst), "l"(src));
}
__device__ __forceinline__ void cpa_commit() { asm volatile("cp.async.commit_group;"); }
__device__ __forceinline__ unsigned sh_addr(const void* p) {
    return (unsigned)__cvta_generic_to_shared(p);
}

// ---------------- producers ----------------
__global__ void split_copy_h(const float* __restrict__ x, __half* __restrict__ h,
                             __half* __restrict__ l, int n4) {
    int i = blockIdx.x * blockDim.x + threadIdx.x;
    if (i < n4) {
        float4 v = ((const float4*)x)[i];
        int b = i * 4;
        __half h0, l0; split2h(v.x, h0, l0); h[b] = h0; l[b] = l0;
        split2h(v.y, h0, l0); h[b+1] = h0; l[b+1] = l0;
        split2h(v.z, h0, l0); h[b+2] = h0; l[b+2] = l0;
        split2h(v.w, h0, l0); h[b+3] = h0; l[b+3] = l0;
    }
}

// weights: W[K][N] -> pairs transposed [N][K]
__global__ void wtsplit(const float* __restrict__ W, __half* __restrict__ th,
                        __half* __restrict__ tl, int K, int N) {
    __shared__ float t[32][33];
    int k0 = blockIdx.x * 32, n0 = blockIdx.y * 32;
    int tx = threadIdx.x, ty = threadIdx.y;
    for (int dy = ty; dy < 32; dy += 8)
        t[dy][tx] = W[(size_t)(k0 + dy) * N + n0 + tx];
    __syncthreads();
    for (int rr = ty; rr < 32; rr += 8) {
        __half h, l; split2h(t[tx][rr], h, l);
        th[(size_t)(n0 + rr) * K + k0 + tx] = h;
        tl[(size_t)(n0 + rr) * K + k0 + tx] = l;
    }
}

__global__ void layernorm_split(const float* __restrict__ x, const float* __restrict__ g,
                                const float* __restrict__ b, __half* __restrict__ yh,
                                __half* __restrict__ yl, int D, float eps) {
    int row = blockIdx.x;
    const float* xr = x + (size_t)row * D;
    float s = 0.f, ss = 0.f;
    for (int i = threadIdx.x; i < D; i += blockDim.x) { float v = xr[i]; s += v; ss += v * v; }
    __shared__ float rs[32], rss[32];
    #pragma unroll
    for (int off = 16; off; off >>= 1) {
        s  += __shfl_xor_sync(0xffffffffu, s,  off);
        ss += __shfl_xor_sync(0xffffffffu, ss, off);
    }
    int w = threadIdx.x >> 5, l = threadIdx.x & 31;
    if (l == 0) { rs[w] = s; rss[w] = ss; }
    __syncthreads();
    int nw = blockDim.x >> 5;
    if (threadIdx.x < 32) {
        s  = (l < nw) ? rs[l]  : 0.f;
        ss = (l < nw) ? rss[l] : 0.f;
        #pragma unroll
        for (int off = 16; off; off >>= 1) {
            s  += __shfl_xor_sync(0xffffffffu, s,  off);
            ss += __shfl_xor_sync(0xffffffffu, ss, off);
        }
        if (l == 0) { rs[0] = s; rss[0] = ss; }
    }
    __syncthreads();
    float mean = rs[0] / (float)D;
    float inv  = rsqrtf(rss[0] / (float)D - mean * mean + eps);
    for (int i = threadIdx.x; i < D; i += blockDim.x) {
        __half h, lo; split2h((xr[i] - mean) * inv * g[i] + b[i], h, lo);
        yh[(size_t)row * D + i] = h; yl[(size_t)row * D + i] = lo;
    }
}

__global__ void rmsnorm_kernel(float* __restrict__ x, const float* __restrict__ g,
                               int D, float eps, float scale) {
    int row = blockIdx.x;
    float* xr = x + (size_t)row * D;
    float ss = 0.f;
    for (int i = threadIdx.x; i < D; i += blockDim.x) { float v = xr[i]; ss += v * v; }
    __shared__ float rss[32];
    #pragma unroll
    for (int off = 16; off; off >>= 1) ss += __shfl_xor_sync(0xffffffffu, ss, off);
    int w = threadIdx.x >> 5, l = threadIdx.x & 31;
    if (l == 0) rss[w] = ss;
    __syncthreads();
    int nw = blockDim.x >> 5;
    if (threadIdx.x < 32) {
        ss = (l < nw) ? rss[l] : 0.f;
        #pragma unroll
        for (int off = 16; off; off >>= 1) ss += __shfl_xor_sync(0xffffffffu, ss, off);
        if (l == 0) rss[0] = ss;
    }
    __syncthreads();
    float inv = rsqrtf(rss[0] / (float)D + eps) * scale;
    for (int i = threadIdx.x; i < D; i += blockDim.x)
        xr[i] = tfbits(xr[i] * inv * g[i]);
}

__global__ void ktrans_kernel(const float* __restrict__ src, float* __restrict__ dst,
                              int srcStride, int colBase, int dBase,
                              const float* __restrict__ lamp, int useLam) {
    __shared__ float t[32][33];
    int bh = blockIdx.z; int b = bh >> 3; int h = bh & 7;
    int j0 = blockIdx.x * 32, d0 = blockIdx.y * 32;
    int tx = threadIdx.x, ty = threadIdx.y;
    float lam = useLam ? lamp[0] : 1.f;
    const float* s = src + ((size_t)(b * NL + j0)) * srcStride + colBase + h * HD + d0;
    for (int dy = ty; dy < 32; dy += 8)
        t[dy][tx] = s[(size_t)dy * srcStride + tx];
    __syncthreads();
    for (int dy = ty; dy < 32; dy += 8)
        dst[((size_t)(bh * 128 + dBase + d0 + dy)) * NL + j0 + tx] = tfbits(lam * t[tx][dy]);
}

// ---------------- fp16 tensor-core GEMM 128x128x32, 3-stage ----------------
// A[M,K] row-major pairs; B stored transposed [N,K] row-major pairs.
// COMP: C = Ah.Bh + Ah.Bl + Al.Bh (compensated).  else: C = Ah.Bh.
// EPI: 0=bias fp32, 1=bias+gelu half(hi), 2=bias+tf32round fp32
#define RSTR 40
#define PLANE_B (128 * RSTR * 2)  // 10240
template <int EPI, bool COMP>
__global__ void __launch_bounds__(256) gemm_h(
    const __half* __restrict__ Ah, const __half* __restrict__ Al,
    const __half* __restrict__ Bh, const __half* __restrict__ Bl,
    const float* __restrict__ bias,
    float* __restrict__ Cf, __half* __restrict__ Chh,
    int M, int K, int N) {
    extern __shared__ char smc[];
    const unsigned smb = sh_addr(smc);
    constexpr unsigned STAGE_B = (COMP ? 4 : 2) * PLANE_B;
    const int tid = threadIdx.x, warp = tid >> 5, lane = tid & 31;
    const int bm = blockIdx.y * 128, bn = blockIdx.x * 128;
    const int wm = (warp & 3) * 32, wn = (warp >> 2) * 64;
    const int g = lane >> 2, tg = lane & 3;
    const int KT = K >> 5;

    float acc[2][8][4];
    #pragma unroll
    for (int i = 0; i < 2; i++)
        #pragma unroll
        for (int j = 0; j < 8; j++)
            #pragma unroll
            for (int k = 0; k < 4; k++) acc[i][j][k] = 0.f;

    auto load_stage = [&](int s, int kt) {
        if (kt < KT) {
            unsigned base = smb + s * STAGE_B;
            #pragma unroll
            for (int i = 0; i < 2; i++) {
                int idx = tid + i * 256;
                int r = idx >> 2, c = idx & 3;
                size_t goA = (size_t)(bm + r) * K + kt * 32 + c * 8;
                size_t goB = (size_t)(bn + r) * K + kt * 32 + c * 8;
                unsigned so = (unsigned)(r * 80 + c * 16);
                cpa16(base + so, Ah + goA);
                cpa16(base + PLANE_B + so, Bh + goB);
                if (COMP) {
                    cpa16(base + 2 * PLANE_B + so, Al + goA);
                    cpa16(base + 3 * PLANE_B + so, Bl + goB);
                }
            }
        }
        cpa_commit();
    };
    load_stage(0, 0);
    load_stage(1, 1);

    const int lrow = lane & 15;
    const int lko = (lane >> 4) * 8;

    for (int kt = 0; kt < KT; kt++) {
        if (kt < KT - 1) asm volatile("cp.async.wait_group 1;" ::: "memory");
        else             asm volatile("cp.async.wait_group 0;" ::: "memory");
        __syncthreads();
        int s = kt % 3;
        if (kt + 2 < KT) load_stage((kt + 2) % 3, kt + 2);
        unsigned aB = smb + s * STAGE_B;
        unsigned bB = aB + PLANE_B;
        #pragma unroll
        for (int ks2 = 0; ks2 < 2; ks2++) {
            int k0 = ks2 * 16;
            unsigned ah[2][4], bh[4][4];
            #pragma unroll
            for (int mt = 0; mt < 2; mt++)
                ldsm4(ah[mt], aB + (unsigned)((wm + mt * 16 + lrow) * RSTR + k0 + lko) * 2);
            #pragma unroll
            for (int nt = 0; nt < 4; nt++)
                ldsm4(bh[nt], bB + (unsigned)((wn + nt * 16 + lrow) * RSTR + k0 + lko) * 2);
            #pragma unroll
            for (int ns = 0; ns < 8; ns++) {
                int nt = ns >> 1, hf = ns & 1;
                unsigned b0 = bh[nt][hf], b1 = bh[nt][hf + 2];
                mma_f16(acc[0][ns], ah[0], b0, b1);
                mma_f16(acc[1][ns], ah[1], b0, b1);
            }
            if (COMP) {
                unsigned al[2][4], bl[4][4];
                #pragma unroll
                for (int mt = 0; mt < 2; mt++)
                    ldsm4(al[mt], aB + 2 * PLANE_B + (unsigned)((wm + mt * 16 + lrow) * RSTR + k0 + lko) * 2);
                #pragma unroll
                for (int nt = 0; nt < 4; nt++)
                    ldsm4(bl[nt], bB + 2 * PLANE_B + (unsigned)((wn + nt * 16 + lrow) * RSTR + k0 + lko) * 2);
                #pragma unroll
                for (int ns = 0; ns < 8; ns++) {
                    int nt = ns >> 1, hf = ns & 1;
                    unsigned bl0 = bl[nt][hf], bl1 = bl[nt][hf + 2];
                    unsigned bh0 = bh[nt][hf], bh1 = bh[nt][hf + 2];
                    mma_f16(acc[0][ns], ah[0], bl0, bl1);
                    mma_f16(acc[1][ns], ah[1], bl0, bl1);
                    mma_f16(acc[0][ns], al[0], bh0, bh1);
                    mma_f16(acc[1][ns], al[1], bh0, bh1);
                }
            }
        }
        __syncthreads();
    }

    #pragma unroll
    for (int mf = 0; mf < 2; mf++) {
        int row = bm + wm + mf * 16 + g;
        #pragma unroll
        for (int nf = 0; nf < 8; nf++) {
            int col = bn + wn + nf * 8 + tg * 2;
            float b0v = bias[col], b1v = bias[col + 1];
            float v00 = acc[mf][nf][0] + b0v, v01 = acc[mf][nf][1] + b1v;
            float v10 = acc[mf][nf][2] + b0v, v11 = acc[mf][nf][3] + b1v;
            if (EPI == 1) {
                __half2 p0, p1;
                p0.x = __float2half_rn(gelu_f(v00)); p0.y = __float2half_rn(gelu_f(v01));
                p1.x = __float2half_rn(gelu_f(v10)); p1.y = __float2half_rn(gelu_f(v11));
                *(__half2*)&Chh[(size_t)row * N + col]       = p0;
                *(__half2*)&Chh[(size_t)(row + 8) * N + col] = p1;
            } else {
                if (EPI == 2) { v00 = tfbits(v00); v01 = tfbits(v01); v10 = tfbits(v10); v11 = tfbits(v11); }
                *(float2*)&Cf[(size_t)row * N + col]       = make_float2(v00, v01);
                *(float2*)&Cf[(size_t)(row + 8) * N + col] = make_float2(v10, v11);
            }
        }
    }
}

// ---------------- legacy-tf32 dual-score flash attention (split-pair output) ----------------
#define QSTR 132
#define KSTR 72
#define PSTR 68
__global__ void __launch_bounds__(256) attn_tc(const float* __restrict__ Qc,
                                               const float* __restrict__ Qv,
                                               const float* __restrict__ Kt,
                                               const float* __restrict__ Vsrc,
                                               __half* __restrict__ outh,
                                               __half* __restrict__ outl) {
    extern __shared__ float sm[];
    float* Qs = sm;
    float* Ks = Qs + 128 * QSTR;
    float* Vs = Ks + 2 * 128 * KSTR;
    float* Ps = Vs + 2 * 64 * KSTR;
    const int tid = threadIdx.x, warp = tid >> 5, lane = tid & 31;
    const int g = lane >> 2, tg = lane & 3;
    const int q0 = blockIdx.x * 128, h = blockIdx.y, b = blockIdx.z;
    const int bh = b * NH + h;
    const unsigned qsb = sh_addr(Qs), ksb = sh_addr(Ks), vsb = sh_addr(Vs), psb = sh_addr(Ps);

    const float* qcb_ = Qc + ((size_t)(b * NQ + q0)) * DI + h * HD;
    const float* qvb_ = Qv + ((size_t)(b * NQ + q0)) * DI + h * HD;
    #pragma unroll
    for (int i = 0; i < 16; i++) {
        int idx = tid + i * 256;
        int r = idx >> 5, q = idx & 31;
        const float* src = (q < 16) ? (qcb_ + (size_t)r * DI + q * 4)
                                    : (qvb_ + (size_t)r * DI + (q - 16) * 4);
        cpa16(qsb + (unsigned)(r * QSTR + q * 4) * 4, src);
    }
    cpa_commit();

    const float* ktb = Kt + (size_t)bh * 128 * NL;
    const float* vvb = Vsrc + (size_t)b * NL * (2 * DI) + h * HD;
    auto load_kv = [&](int s, int m0) {
        unsigned ks_ = ksb + s * (128 * KSTR * 4);
        unsigned vs_ = vsb + s * (64 * KSTR * 4);
        #pragma unroll
        for (int i = 0; i < 8; i++) {
            int idx = tid + i * 256;
            int r = idx >> 4, q = idx & 15;
            cpa16(ks_ + (unsigned)(r * KSTR + q * 4) * 4, ktb + (size_t)r * NL + m0 + q * 4);
        }
        #pragma unroll
        for (int i = 0; i < 4; i++) {
            int idx = tid + i * 256;
            int r = idx >> 4, q = idx & 15;
            cpa16(vs_ + (unsigned)(r * KSTR + q * 4) * 4, vvb + (size_t)(m0 + r) * (2 * DI) + q * 4);
        }
        cpa_commit();
    };
    load_kv(0, 0);
    load_kv(1, 64);

    float m_[2] = {-1e30f, -1e30f}, l_[2] = {0.f, 0.f};
    float o[8][4];
    #pragma unroll
    for (int i = 0; i < 8; i++)
        #pragma unroll
        for (int j = 0; j < 4; j++) o[i][j] = 0.f;

    const int wrow = warp * 16;
    const int lrow = (lane & 7) + ((lane >> 3) & 1) * 8;
    const int lcol = (lane >> 4) * 4;
    const int NIT = NL / 64;

    for (int it = 0; it < NIT; it++) {
        if (it < NIT - 1) asm volatile("cp.async.wait_group 1;");
        else              asm volatile("cp.async.wait_group 0;");
        __syncthreads();
        int s = it & 1;
        const float* ksp = Ks + s * 128 * KSTR;
        const float* vsp = Vs + s * 64 * KSTR;

        float sacc[8][4];
        #pragma unroll
        for (int i = 0; i < 8; i++)
            #pragma unroll
            for (int j = 0; j < 4; j++) sacc[i][j] = 0.f;
        #pragma unroll
        for (int ks2 = 0; ks2 < 16; ks2++) {
            int k0 = ks2 * 8;
            unsigned a[4];
            ldsm4(a, qsb + (unsigned)((wrow + lrow) * QSTR + k0 + lcol) * 4);
            #pragma unroll
            for (int nf = 0; nf < 8; nf++) {
                unsigned b0 = __float_as_uint(ksp[(k0 + tg) * KSTR + nf * 8 + g]);
                unsigned b1 = __float_as_uint(ksp[(k0 + tg + 4) * KSTR + nf * 8 + g]);
                mma_tf32(sacc[nf], a, b0, b1);
            }
        }

        #pragma unroll
        for (int rw = 0; rw < 2; rw++) {
            float mx = -1e30f;
            #pragma unroll
            for (int nf = 0; nf < 8; nf++)
                mx = fmaxf(mx, fmaxf(sacc[nf][2 * rw], sacc[nf][2 * rw + 1]));
            mx = fmaxf(mx, __shfl_xor_sync(0xffffffffu, mx, 1));
            mx = fmaxf(mx, __shfl_xor_sync(0xffffffffu, mx, 2));
            float mn = fmaxf(m_[rw], mx);
            float corr = __expf(m_[rw] - mn);
            m_[rw] = mn;
            float sum = 0.f;
            int prow = wrow + rw * 8 + g;
            #pragma unroll
            for (int nf = 0; nf < 8; nf++) {
                float p0 = __expf(sacc[nf][2 * rw] - mn);
                float p1 = __expf(sacc[nf][2 * rw + 1] - mn);
                sum += p0 + p1;
                *(uint2*)(Ps + prow * PSTR + nf * 8 + tg * 2) = make_uint2(f2tf(p0), f2tf(p1));
            }
            sum += __shfl_xor_sync(0xffffffffu, sum, 1);
            sum += __shfl_xor_sync(0xffffffffu, sum, 2);
            l_[rw] = l_[rw] * corr + sum;
            #pragma unroll
            for (int nf = 0; nf < 8; nf++) {
                o[nf][2 * rw]     *= corr;
                o[nf][2 * rw + 1] *= corr;
            }
        }
        __syncwarp();

        #pragma unroll
        for (int ks2 = 0; ks2 < 8; ks2++) {
            int k0 = ks2 * 8;
            unsigned a[4];
            ldsm4(a, psb + (unsigned)((wrow + lrow) * PSTR + k0 + lcol) * 4);
            #pragma unroll
            for (int nf = 0; nf < 8; nf++) {
                unsigned b0 = __float_as_uint(vsp[(k0 + tg) * KSTR + nf * 8 + g]);
                unsigned b1 = __float_as_uint(vsp[(k0 + tg + 4) * KSTR + nf * 8 + g]);
                mma_tf32(o[nf], a, b0, b1);
            }
        }
        __syncthreads();
        if (it + 2 < NIT) load_kv(s, (it + 2) * 64);
    }

    #pragma unroll
    for (int rw = 0; rw < 2; rw++) {
        float inv = 1.f / l_[rw];
        int row = b * NQ + q0 + wrow + rw * 8 + g;
        #pragma unroll
        for (int nf = 0; nf < 8; nf++) {
            int col = h * HD + nf * 8 + tg * 2;
            __half2 hv, lv;
            __half hh, ll;
            split2h(o[nf][2 * rw] * inv, hh, ll);     hv.x = hh; lv.x = ll;
            split2h(o[nf][2 * rw + 1] * inv, hh, ll); hv.y = hh; lv.y = ll;
            *(__half2*)&outh[(size_t)row * DI + col] = hv;
            *(__half2*)&outl[(size_t)row * DI + col] = lv;
        }
    }
}

// ---------------- host launcher ----------------
extern "C" void kernel_launch(void* const* d_in, const int* in_sizes, int n_in,
                              void* d_out, int out_size) {
    const float* coords = (const float*)d_in[0];
    const float* values = (const float*)d_in[1];
    const float* Lv     = (const float*)d_in[2];
    const float* Lc     = (const float*)d_in[3];
    const float* lam    = (const float*)d_in[4];
    const float* lvn_g  = (const float*)d_in[5];
    const float* lvn_b  = (const float*)d_in[6];
    const float* lcn_g  = (const float*)d_in[7];
    const float* lcn_b  = (const float*)d_in[8];
    const float* ck_w   = (const float*)d_in[9];
    const float* ck_b   = (const float*)d_in[10];
    const float* ck_g   = (const float*)d_in[11];
    const float* cq_w   = (const float*)d_in[12];
    const float* cq_b   = (const float*)d_in[13];
    const float* cq_g   = (const float*)d_in[14];
    const float* vq_w   = (const float*)d_in[15];
    const float* vq_b   = (const float*)d_in[16];
    const float* vq_g   = (const float*)d_in[17];
    const float* vk_w   = (const float*)d_in[18];
    const float* vk_b   = (const float*)d_in[19];
    const float* op_w   = (const float*)d_in[20];
    const float* op_b   = (const float*)d_in[21];
    const float* oln_g  = (const float*)d_in[22];
    const float* oln_b  = (const float*)d_in[23];
    const float* m1_w   = (const float*)d_in[24];
    const float* m1_b   = (const float*)d_in[25];
    const float* m2_w   = (const float*)d_in[26];
    const float* m2_b   = (const float*)d_in[27];
    const float* m3_w   = (const float*)d_in[28];
    const float* m3_b   = (const float*)d_in[29];
    float* out = (float*)d_out;

    float *vkb, *kcb, *qvb, *qcb, *yb, *ktb;
    cudaGetSymbolAddress((void**)&vkb, g_vk);
    cudaGetSymbolAddress((void**)&kcb, g_kc);
    cudaGetSymbolAddress((void**)&qvb, g_qv);
    cudaGetSymbolAddress((void**)&qcb, g_qc);
    cudaGetSymbolAddress((void**)&yb,  g_y);
    cudaGetSymbolAddress((void**)&ktb, g_kt);
    __half *sLvh, *sLvl, *sLch, *sLcl, *valh, *vall, *crdh, *crdl;
    __half *atth, *attl, *ybsh, *ybsl, *h1h, *h2h, *wth, *wtl;
    cudaGetSymbolAddress((void**)&sLvh, g_sLv_h); cudaGetSymbolAddress((void**)&sLvl, g_sLv_l);
    cudaGetSymbolAddress((void**)&sLch, g_sLc_h); cudaGetSymbolAddress((void**)&sLcl, g_sLc_l);
    cudaGetSymbolAddress((void**)&valh, g_val_h); cudaGetSymbolAddress((void**)&vall, g_val_l);
    cudaGetSymbolAddress((void**)&crdh, g_crd_h); cudaGetSymbolAddress((void**)&crdl, g_crd_l);
    cudaGetSymbolAddress((void**)&atth, g_att_h); cudaGetSymbolAddress((void**)&attl, g_att_l);
    cudaGetSymbolAddress((void**)&ybsh, g_ybs_h); cudaGetSymbolAddress((void**)&ybsl, g_ybs_l);
    cudaGetSymbolAddress((void**)&h1h,  g_h1_h);
    cudaGetSymbolAddress((void**)&h2h,  g_h2_h);
    cudaGetSymbolAddress((void**)&wth,  g_wth);   cudaGetSymbolAddress((void**)&wtl,  g_wtl);

    const int BNL = BATCH * NL;
    const int BNQ = BATCH * NQ;
    const int GSMC = 3 * 4 * PLANE_B;  // 122880 (compensated)
    const int GSM1 = 3 * 2 * PLANE_B;  // 61440
    const int ATTN_SMEM = (128 * QSTR + 2 * 128 * KSTR + 2 * 64 * KSTR + 128 * PSTR) * 4;
    cudaFuncSetAttribute((const void*)gemm_h<0, true>,  cudaFuncAttributeMaxDynamicSharedMemorySize, GSMC);
    cudaFuncSetAttribute((const void*)gemm_h<2, true>,  cudaFuncAttributeMaxDynamicSharedMemorySize, GSMC);
    cudaFuncSetAttribute((const void*)gemm_h<1, false>, cudaFuncAttributeMaxDynamicSharedMemorySize, GSM1);
    cudaFuncSetAttribute((const void*)gemm_h<0, false>, cudaFuncAttributeMaxDynamicSharedMemorySize, GSM1);
    cudaFuncSetAttribute(attn_tc, cudaFuncAttributeMaxDynamicSharedMemorySize, ATTN_SMEM);

    // weight splits (transposed [N][K] pairs)
    dim3 wtb(32, 8);
    wtsplit<<<dim3(DC/32, DI/32), wtb>>>(ck_w, wth + OFF_CKW, wtl + OFF_CKW, DC, DI);
    wtsplit<<<dim3(DC/32, DI/32), wtb>>>(cq_w, wth + OFF_CQW, wtl + OFF_CQW, DC, DI);
    wtsplit<<<dim3(DV/32, DI/32), wtb>>>(vq_w, wth + OFF_VQW, wtl + OFF_VQW, DV, DI);
    wtsplit<<<dim3(DV/32, 2*DI/32), wtb>>>(vk_w, wth + OFF_VKW, wtl + OFF_VKW, DV, 2*DI);
    wtsplit<<<dim3(DI/32, DV/32), wtb>>>(op_w, wth + OFF_OPW, wtl + OFF_OPW, DI, DV);
    wtsplit<<<dim3(DV/32, DF/32), wtb>>>(m1_w, wth + OFF_M1W, wtl + OFF_M1W, DV, DF);
    wtsplit<<<dim3(DF/32, DF/32), wtb>>>(m2_w, wth + OFF_M2W, wtl + OFF_M2W, DF, DF);
    wtsplit<<<dim3(DF/32, DV/32), wtb>>>(m3_w, wth + OFF_M3W, wtl + OFF_M3W, DF, DV);

    // input splits + latent layernorms
    split_copy_h<<<BNQ * DV / 4 / 256, 256>>>(values, valh, vall, BNQ * DV / 4);
    split_copy_h<<<BNQ * DC / 4 / 256, 256>>>(coords, crdh, crdl, BNQ * DC / 4);
    layernorm_split<<<BNL, 256>>>(Lv, lvn_g, lvn_b, sLvh, sLvl, DV, 1e-5f);
    layernorm_split<<<BNL, 128>>>(Lc, lcn_g, lcn_b, sLch, sLcl, DC, 1e-5f);

    // projections (compensated fp16): effectively exact
    gemm_h<2, true><<<dim3(8, 32), 256, GSMC>>>(sLvh, sLvl, wth + OFF_VKW, wtl + OFF_VKW,
                                                vk_b, vkb, (__half*)0, BNL, DV, 2 * DI);
    gemm_h<0, true><<<dim3(4, 32), 256, GSMC>>>(sLch, sLcl, wth + OFF_CKW, wtl + OFF_CKW,
                                                ck_b, kcb, (__half*)0, BNL, DC, DI);
    rmsnorm_kernel<<<BNL, 256>>>(kcb, ck_g, DI, 1e-6f, 1.0f);
    gemm_h<0, true><<<dim3(4, 128), 256, GSMC>>>(valh, vall, wth + OFF_VQW, wtl + OFF_VQW,
                                                 vq_b, qvb, (__half*)0, BNQ, DV, DI);
    rmsnorm_kernel<<<BNQ, 256>>>(qvb, vq_g, DI, 1e-6f, 0.125f);
    gemm_h<0, true><<<dim3(4, 128), 256, GSMC>>>(crdh, crdl, wth + OFF_CQW, wtl + OFF_CQW,
                                                 cq_b, qcb, (__half*)0, BNQ, DC, DI);
    rmsnorm_kernel<<<BNQ, 256>>>(qcb, cq_g, DI, 1e-6f, 0.125f);

    // K transposes (k_c plain, k_v scaled by lambda), tf32-rounded
    dim3 tb(32, 8);
    ktrans_kernel<<<dim3(NL/32, 2, BATCH*NH), tb>>>(kcb, ktb, DI, 0, 0, lam, 0);
    ktrans_kernel<<<dim3(NL/32, 2, BATCH*NH), tb>>>(vkb, ktb, 2*DI, DI, 64, lam, 1);

    // attention (tf32, split-pair output)
    attn_tc<<<dim3(NQ/128, NH, BATCH), 256, ATTN_SMEM>>>(qcb, qvb, ktb, vkb, atth, attl);

    // output projection (compensated) + LN + MLP (fp16 single-pass)
    gemm_h<0, true><<<dim3(4, 128), 256, GSMC>>>(atth, attl, wth + OFF_OPW, wtl + OFF_OPW,
                                                 op_b, yb, (__half*)0, BNQ, DI, DV);
    layernorm_split<<<BNQ, 256>>>(yb, oln_g, oln_b, ybsh, ybsl, DV, 1e-5f);
    gemm_h<1, false><<<dim3(16, 128), 256, GSM1>>>(ybsh, (__half*)0, wth + OFF_M1W, (__half*)0,
                                                   m1_b, (float*)0, h1h, BNQ, DV, DF);
    gemm_h<1, false><<<dim3(16, 128), 256, GSM1>>>(h1h, (__half*)0, wth + OFF_M2W, (__half*)0,
                                                   m2_b, (float*)0, h2h, BNQ, DF, DF);
    gemm_h<0, false><<<dim3(4, 128), 256, GSM1>>>(h2h, (__half*)0, wth + OFF_M3W, (__half*)0,
                                                  m3_b, out, (__half*)0, BNQ, DF, DV);
}